// round 13
// baseline (speedup 1.0000x reference)
#include <cuda_runtime.h>

#define V_N   262144
#define E_N   786432
#define CIMG  256
#define HID   128
#define HWI   64
#define DIN   131

// Scratch (device globals: allocation-free per harness rules)
__device__ float g_feats[(size_t)V_N * HID];  // current vert_feats (non-pos part)
__device__ float g_y[(size_t)V_N * HID];      // y = A@w0+b0, then += neighbor sum
__device__ float g_z[(size_t)V_N * HID];      // z = A@w1+b1

#define BM 128
#define BN 128
#define BK 16
#define PADF 4

// ---------------------------------------------------------------------------
// Kernel 1: fused bilinear vert_align + bottleneck GEMM + bias + ReLU
//   g_feats[v, :] = relu( sample(img, verts[v,:2]) @ Wb + bb )
// A (V x 256) is generated on the fly in the A-tile loader.
// ---------------------------------------------------------------------------
__global__ __launch_bounds__(256, 2) void k_img_bottleneck(
    const float* __restrict__ img, const float* __restrict__ verts,
    const float* __restrict__ Wb, const float* __restrict__ bb)
{
    __shared__ __align__(16) float As[BK][BM + PADF];
    __shared__ __align__(16) float Bs[BK][BN + PADF];

    const int tid = threadIdx.x;
    const int tx = tid & 15, ty = tid >> 4;
    const int gm0 = blockIdx.x * BM;

    // This thread owns column m of the A tile; sampling params fixed per thread.
    const int m  = tid & 127;
    const int kq = tid >> 7;  // 0/1: which 8 k-rows this thread fills
    const int gm = gm0 + m;

    float vx = verts[gm * 3 + 0];
    float vy = verts[gm * 3 + 1];
    float px = (vx + 1.0f) * 0.5f * (float)(HWI - 1);
    float py = (vy + 1.0f) * 0.5f * (float)(HWI - 1);
    float fx = floorf(px), fy = floorf(py);
    float wx = px - fx, wy = py - fy;
    int x0 = (int)fx; x0 = max(0, min(x0, HWI - 1));
    int x1 = min(x0 + 1, HWI - 1);
    int y0 = (int)fy; y0 = max(0, min(y0, HWI - 1));
    int y1 = min(y0 + 1, HWI - 1);
    float w00 = (1.0f - wx) * (1.0f - wy);
    float w01 = wx * (1.0f - wy);
    float w10 = (1.0f - wx) * wy;
    float w11 = wx * wy;
    int i00 = y0 * HWI + x0, i01 = y0 * HWI + x1;
    int i10 = y1 * HWI + x0, i11 = y1 * HWI + x1;

    float acc[8][8];
#pragma unroll
    for (int i = 0; i < 8; i++)
#pragma unroll
        for (int j = 0; j < 8; j++) acc[i][j] = 0.0f;

    for (int kt = 0; kt < CIMG; kt += BK) {
        // A tile: sample 8 channels for this thread's vertex
#pragma unroll
        for (int j = 0; j < 8; j++) {
            int k = kt + kq * 8 + j;
            const float* ch = img + (size_t)k * (HWI * HWI);
            float val = ch[i00] * w00 + ch[i01] * w01 + ch[i10] * w10 + ch[i11] * w11;
            As[kq * 8 + j][m] = val;
        }
        // B tile: Wb is (256,128) row-major
#pragma unroll
        for (int r = 0; r < 2; r++) {
            int idx = tid + r * 256;
            int k = idx >> 5, n4 = (idx & 31) << 2;
            *(float4*)&Bs[k][n4] = *(const float4*)&Wb[(size_t)(kt + k) * HID + n4];
        }
        __syncthreads();
#pragma unroll
        for (int kk = 0; kk < BK; kk++) {
            float a[8], b[8];
            *(float4*)&a[0] = *(float4*)&As[kk][ty * 8];
            *(float4*)&a[4] = *(float4*)&As[kk][ty * 8 + 4];
            *(float4*)&b[0] = *(float4*)&Bs[kk][tx * 8];
            *(float4*)&b[4] = *(float4*)&Bs[kk][tx * 8 + 4];
#pragma unroll
            for (int i = 0; i < 8; i++)
#pragma unroll
                for (int j = 0; j < 8; j++) acc[i][j] += a[i] * b[j];
        }
        __syncthreads();
    }

    float bv[8];
    *(float4*)&bv[0] = *(const float4*)&bb[tx * 8];
    *(float4*)&bv[4] = *(const float4*)&bb[tx * 8 + 4];
#pragma unroll
    for (int i = 0; i < 8; i++) {
        int row = gm0 + ty * 8 + i;
        float4 o0, o1;
        o0.x = fmaxf(acc[i][0] + bv[0], 0.0f);
        o0.y = fmaxf(acc[i][1] + bv[1], 0.0f);
        o0.z = fmaxf(acc[i][2] + bv[2], 0.0f);
        o0.w = fmaxf(acc[i][3] + bv[3], 0.0f);
        o1.x = fmaxf(acc[i][4] + bv[4], 0.0f);
        o1.y = fmaxf(acc[i][5] + bv[5], 0.0f);
        o1.z = fmaxf(acc[i][6] + bv[6], 0.0f);
        o1.w = fmaxf(acc[i][7] + bv[7], 0.0f);
        *(float4*)&g_feats[(size_t)row * HID + tx * 8]     = o0;
        *(float4*)&g_feats[(size_t)row * HID + tx * 8 + 4] = o1;
    }
}

// ---------------------------------------------------------------------------
// Kernel 2: GCN layer GEMMs. A = [g_feats | verts] (V x 131).
// blockIdx.y == 0 -> g_y = A@W0 + b0 ; blockIdx.y == 1 -> g_z = A@W1 + b1
// ---------------------------------------------------------------------------
__global__ __launch_bounds__(256, 2) void k_gcn_gemm(
    const float* __restrict__ verts,
    const float* __restrict__ W0, const float* __restrict__ B0,
    const float* __restrict__ W1, const float* __restrict__ B1)
{
    __shared__ __align__(16) float As[BK][BM + PADF];
    __shared__ __align__(16) float Bs[BK][BN + PADF];

    const int tid = threadIdx.x;
    const int tx = tid & 15, ty = tid >> 4;
    const int gm0 = blockIdx.x * BM;

    const float* W  = (blockIdx.y == 0) ? W0 : W1;
    const float* Bb = (blockIdx.y == 0) ? B0 : B1;
    float* outp     = (blockIdx.y == 0) ? g_y : g_z;

    float acc[8][8];
#pragma unroll
    for (int i = 0; i < 8; i++)
#pragma unroll
        for (int j = 0; j < 8; j++) acc[i][j] = 0.0f;

    for (int kt = 0; kt < 144; kt += BK) {   // 9 tiles; last covers k=128..130 + zero pad
        if (kt < HID) {
#pragma unroll
            for (int r = 0; r < 2; r++) {
                int idx = tid + r * 256;
                int mm = idx >> 2;
                int k4 = (idx & 3) << 2;
                float4 v = *(const float4*)&g_feats[(size_t)(gm0 + mm) * HID + kt + k4];
                As[k4 + 0][mm] = v.x;
                As[k4 + 1][mm] = v.y;
                As[k4 + 2][mm] = v.z;
                As[k4 + 3][mm] = v.w;
            }
        } else {
#pragma unroll
            for (int r = 0; r < 8; r++) {
                int idx = tid + r * 256;
                int mm = idx & 127;
                int kl = idx >> 7;
                float v = (kl < 3) ? verts[(size_t)(gm0 + mm) * 3 + kl] : 0.0f;
                As[kl][mm] = v;
            }
        }
#pragma unroll
        for (int r = 0; r < 2; r++) {
            int idx = tid + r * 256;
            int k = idx >> 5, n4 = (idx & 31) << 2;
            int kg = kt + k;
            float4 v = make_float4(0.f, 0.f, 0.f, 0.f);
            if (kg < DIN) v = *(const float4*)&W[(size_t)kg * HID + n4];
            *(float4*)&Bs[k][n4] = v;
        }
        __syncthreads();
#pragma unroll
        for (int kk = 0; kk < BK; kk++) {
            float a[8], b[8];
            *(float4*)&a[0] = *(float4*)&As[kk][ty * 8];
            *(float4*)&a[4] = *(float4*)&As[kk][ty * 8 + 4];
            *(float4*)&b[0] = *(float4*)&Bs[kk][tx * 8];
            *(float4*)&b[4] = *(float4*)&Bs[kk][tx * 8 + 4];
#pragma unroll
            for (int i = 0; i < 8; i++)
#pragma unroll
                for (int j = 0; j < 8; j++) acc[i][j] += a[i] * b[j];
        }
        __syncthreads();
    }

    float bv[8];
    *(float4*)&bv[0] = *(const float4*)&Bb[tx * 8];
    *(float4*)&bv[4] = *(const float4*)&Bb[tx * 8 + 4];
#pragma unroll
    for (int i = 0; i < 8; i++) {
        int row = gm0 + ty * 8 + i;
        float4 o0, o1;
        o0.x = acc[i][0] + bv[0]; o0.y = acc[i][1] + bv[1];
        o0.z = acc[i][2] + bv[2]; o0.w = acc[i][3] + bv[3];
        o1.x = acc[i][4] + bv[4]; o1.y = acc[i][5] + bv[5];
        o1.z = acc[i][6] + bv[6]; o1.w = acc[i][7] + bv[7];
        *(float4*)&outp[(size_t)row * HID + tx * 8]     = o0;
        *(float4*)&outp[(size_t)row * HID + tx * 8 + 4] = o1;
    }
}

// ---------------------------------------------------------------------------
// Kernel 3: edge scatter. y[e0] += z[e1]; y[e1] += z[e0]. Warp per edge.
// ---------------------------------------------------------------------------
__global__ void k_scatter(const int* __restrict__ edges)
{
    int t = blockIdx.x * blockDim.x + threadIdx.x;
    int e = t >> 5;
    if (e >= E_N) return;
    int c = (t & 31) << 2;
    int a = edges[2 * e + 0];
    int b = edges[2 * e + 1];
    float4 za = *(const float4*)&g_z[(size_t)a * HID + c];
    float4 zb = *(const float4*)&g_z[(size_t)b * HID + c];
    float* ya = &g_y[(size_t)a * HID + c];
    float* yb = &g_y[(size_t)b * HID + c];
    atomicAdd(ya + 0, zb.x); atomicAdd(ya + 1, zb.y);
    atomicAdd(ya + 2, zb.z); atomicAdd(ya + 3, zb.w);
    atomicAdd(yb + 0, za.x); atomicAdd(yb + 1, za.y);
    atomicAdd(yb + 2, za.z); atomicAdd(yb + 3, za.w);
}

// ---------------------------------------------------------------------------
// Kernel 4: g_feats = relu(g_y); optionally also write to output slice.
// ---------------------------------------------------------------------------
__global__ void k_relu(float* __restrict__ out_opt)
{
    size_t i = (size_t)(blockIdx.x * blockDim.x + threadIdx.x) * 4;
    float4 v = *(float4*)&g_y[i];
    v.x = fmaxf(v.x, 0.0f);
    v.y = fmaxf(v.y, 0.0f);
    v.z = fmaxf(v.z, 0.0f);
    v.w = fmaxf(v.w, 0.0f);
    *(float4*)&g_feats[i] = v;
    if (out_opt) *(float4*)&out_opt[i] = v;
}

// ---------------------------------------------------------------------------
// Kernel 5: offset head. new_verts = verts + tanh([feats|verts] @ ow + ob)
// Warp per vertex.
// ---------------------------------------------------------------------------
__global__ void k_offset(const float* __restrict__ verts,
                         const float* __restrict__ ow,
                         const float* __restrict__ ob,
                         float* __restrict__ out)
{
    int gt = blockIdx.x * blockDim.x + threadIdx.x;
    int v = gt >> 5, lane = gt & 31;
    if (v >= V_N) return;
    float a0 = 0.f, a1 = 0.f, a2 = 0.f;
    for (int k = lane; k < DIN; k += 32) {
        float f = (k < HID) ? g_feats[(size_t)v * HID + k]
                            : verts[(size_t)v * 3 + (k - HID)];
        a0 += f * ow[k * 3 + 0];
        a1 += f * ow[k * 3 + 1];
        a2 += f * ow[k * 3 + 2];
    }
#pragma unroll
    for (int o = 16; o; o >>= 1) {
        a0 += __shfl_xor_sync(0xffffffffu, a0, o);
        a1 += __shfl_xor_sync(0xffffffffu, a1, o);
        a2 += __shfl_xor_sync(0xffffffffu, a2, o);
    }
    if (lane == 0) {
        out[(size_t)v * 3 + 0] = verts[(size_t)v * 3 + 0] + tanhf(a0 + ob[0]);
        out[(size_t)v * 3 + 1] = verts[(size_t)v * 3 + 1] + tanhf(a1 + ob[1]);
        out[(size_t)v * 3 + 2] = verts[(size_t)v * 3 + 2] + tanhf(a2 + ob[2]);
    }
}

// ---------------------------------------------------------------------------
extern "C" void kernel_launch(void* const* d_in, const int* in_sizes, int n_in,
                              void* d_out, int out_size)
{
    const float* x     = (const float*)d_in[0];
    const float* verts = (const float*)d_in[1];
    const int*   edges = (const int*)d_in[2];
    const float* bw    = (const float*)d_in[3];
    const float* bb    = (const float*)d_in[4];
    const float* w0    = (const float*)d_in[5];
    const float* b0    = (const float*)d_in[6];
    const float* w1    = (const float*)d_in[7];
    const float* b1    = (const float*)d_in[8];
    const float* ow    = (const float*)d_in[9];
    const float* ob    = (const float*)d_in[10];
    float* out = (float*)d_out;

    // Stage 1: fused sample + bottleneck
    k_img_bottleneck<<<V_N / BM, 256>>>(x, verts, bw, bb);

    // Stage 2: 3 GCN layers
    for (int l = 0; l < 3; l++) {
        dim3 grid(V_N / BM, 2);
        k_gcn_gemm<<<grid, 256>>>(verts,
                                  w0 + (size_t)l * DIN * HID, b0 + (size_t)l * HID,
                                  w1 + (size_t)l * DIN * HID, b1 + (size_t)l * HID);
        k_scatter<<<(E_N * 32) / 256, 256>>>(edges);

        float* out_feats = nullptr;
        if (l == 2 && out_size >= (int)((size_t)V_N * 3 + (size_t)V_N * HID))
            out_feats = out + (size_t)V_N * 3;
        k_relu<<<((size_t)V_N * HID / 4) / 256, 256>>>(out_feats);
    }

    // Stage 3: offset head -> new_verts
    k_offset<<<(V_N * 32) / 256, 256>>>(verts, ow, ob, out);
}

// round 14
// speedup vs baseline: 1.0019x; 1.0019x over previous
#include <cuda_runtime.h>

#define V_N   262144
#define E_N   786432
#define CIMG  256
#define HID   128
#define HWI   64
#define DIN   131

// Scratch (device globals: allocation-free per harness rules)
__device__ float g_feats[(size_t)V_N * HID];  // current vert_feats (non-pos part)
__device__ float g_y[(size_t)V_N * HID];      // y = A@w0+b0, then += neighbor sum
__device__ float g_z[(size_t)V_N * HID];      // z = A@w1+b1

#define BM 128
#define BN 128
#define BK 16
#define PADF 4

// ---------------------------------------------------------------------------
// Kernel 1: fused bilinear vert_align + bottleneck GEMM + bias + ReLU
//   g_feats[v, :] = relu( sample(img, verts[v,:2]) @ Wb + bb )
// A (V x 256) is generated on the fly in the A-tile loader.
// ---------------------------------------------------------------------------
__global__ __launch_bounds__(256, 2) void k_img_bottleneck(
    const float* __restrict__ img, const float* __restrict__ verts,
    const float* __restrict__ Wb, const float* __restrict__ bb)
{
    __shared__ __align__(16) float As[BK][BM + PADF];
    __shared__ __align__(16) float Bs[BK][BN + PADF];

    const int tid = threadIdx.x;
    const int tx = tid & 15, ty = tid >> 4;
    const int gm0 = blockIdx.x * BM;

    // This thread owns column m of the A tile; sampling params fixed per thread.
    const int m  = tid & 127;
    const int kq = tid >> 7;  // 0/1: which 8 k-rows this thread fills
    const int gm = gm0 + m;

    float vx = verts[gm * 3 + 0];
    float vy = verts[gm * 3 + 1];
    float px = (vx + 1.0f) * 0.5f * (float)(HWI - 1);
    float py = (vy + 1.0f) * 0.5f * (float)(HWI - 1);
    float fx = floorf(px), fy = floorf(py);
    float wx = px - fx, wy = py - fy;
    int x0 = (int)fx; x0 = max(0, min(x0, HWI - 1));
    int x1 = min(x0 + 1, HWI - 1);
    int y0 = (int)fy; y0 = max(0, min(y0, HWI - 1));
    int y1 = min(y0 + 1, HWI - 1);
    float w00 = (1.0f - wx) * (1.0f - wy);
    float w01 = wx * (1.0f - wy);
    float w10 = (1.0f - wx) * wy;
    float w11 = wx * wy;
    int i00 = y0 * HWI + x0, i01 = y0 * HWI + x1;
    int i10 = y1 * HWI + x0, i11 = y1 * HWI + x1;

    float acc[8][8];
#pragma unroll
    for (int i = 0; i < 8; i++)
#pragma unroll
        for (int j = 0; j < 8; j++) acc[i][j] = 0.0f;

    for (int kt = 0; kt < CIMG; kt += BK) {
        // A tile: sample 8 channels for this thread's vertex
#pragma unroll
        for (int j = 0; j < 8; j++) {
            int k = kt + kq * 8 + j;
            const float* ch = img + (size_t)k * (HWI * HWI);
            float val = ch[i00] * w00 + ch[i01] * w01 + ch[i10] * w10 + ch[i11] * w11;
            As[kq * 8 + j][m] = val;
        }
        // B tile: Wb is (256,128) row-major
#pragma unroll
        for (int r = 0; r < 2; r++) {
            int idx = tid + r * 256;
            int k = idx >> 5, n4 = (idx & 31) << 2;
            *(float4*)&Bs[k][n4] = *(const float4*)&Wb[(size_t)(kt + k) * HID + n4];
        }
        __syncthreads();
#pragma unroll
        for (int kk = 0; kk < BK; kk++) {
            float a[8], b[8];
            *(float4*)&a[0] = *(float4*)&As[kk][ty * 8];
            *(float4*)&a[4] = *(float4*)&As[kk][ty * 8 + 4];
            *(float4*)&b[0] = *(float4*)&Bs[kk][tx * 8];
            *(float4*)&b[4] = *(float4*)&Bs[kk][tx * 8 + 4];
#pragma unroll
            for (int i = 0; i < 8; i++)
#pragma unroll
                for (int j = 0; j < 8; j++) acc[i][j] += a[i] * b[j];
        }
        __syncthreads();
    }

    float bv[8];
    *(float4*)&bv[0] = *(const float4*)&bb[tx * 8];
    *(float4*)&bv[4] = *(const float4*)&bb[tx * 8 + 4];
#pragma unroll
    for (int i = 0; i < 8; i++) {
        int row = gm0 + ty * 8 + i;
        float4 o0, o1;
        o0.x = fmaxf(acc[i][0] + bv[0], 0.0f);
        o0.y = fmaxf(acc[i][1] + bv[1], 0.0f);
        o0.z = fmaxf(acc[i][2] + bv[2], 0.0f);
        o0.w = fmaxf(acc[i][3] + bv[3], 0.0f);
        o1.x = fmaxf(acc[i][4] + bv[4], 0.0f);
        o1.y = fmaxf(acc[i][5] + bv[5], 0.0f);
        o1.z = fmaxf(acc[i][6] + bv[6], 0.0f);
        o1.w = fmaxf(acc[i][7] + bv[7], 0.0f);
        *(float4*)&g_feats[(size_t)row * HID + tx * 8]     = o0;
        *(float4*)&g_feats[(size_t)row * HID + tx * 8 + 4] = o1;
    }
}

// ---------------------------------------------------------------------------
// Kernel 2: GCN layer GEMMs. A = [g_feats | verts] (V x 131).
// blockIdx.y == 0 -> g_y = A@W0 + b0 ; blockIdx.y == 1 -> g_z = A@W1 + b1
// ---------------------------------------------------------------------------
__global__ __launch_bounds__(256, 2) void k_gcn_gemm(
    const float* __restrict__ verts,
    const float* __restrict__ W0, const float* __restrict__ B0,
    const float* __restrict__ W1, const float* __restrict__ B1)
{
    __shared__ __align__(16) float As[BK][BM + PADF];
    __shared__ __align__(16) float Bs[BK][BN + PADF];

    const int tid = threadIdx.x;
    const int tx = tid & 15, ty = tid >> 4;
    const int gm0 = blockIdx.x * BM;

    const float* W  = (blockIdx.y == 0) ? W0 : W1;
    const float* Bb = (blockIdx.y == 0) ? B0 : B1;
    float* outp     = (blockIdx.y == 0) ? g_y : g_z;

    float acc[8][8];
#pragma unroll
    for (int i = 0; i < 8; i++)
#pragma unroll
        for (int j = 0; j < 8; j++) acc[i][j] = 0.0f;

    for (int kt = 0; kt < 144; kt += BK) {   // 9 tiles; last covers k=128..130 + zero pad
        if (kt < HID) {
#pragma unroll
            for (int r = 0; r < 2; r++) {
                int idx = tid + r * 256;
                int mm = idx >> 2;
                int k4 = (idx & 3) << 2;
                float4 v = *(const float4*)&g_feats[(size_t)(gm0 + mm) * HID + kt + k4];
                As[k4 + 0][mm] = v.x;
                As[k4 + 1][mm] = v.y;
                As[k4 + 2][mm] = v.z;
                As[k4 + 3][mm] = v.w;
            }
        } else {
#pragma unroll
            for (int r = 0; r < 8; r++) {
                int idx = tid + r * 256;
                int mm = idx & 127;
                int kl = idx >> 7;
                float v = (kl < 3) ? verts[(size_t)(gm0 + mm) * 3 + kl] : 0.0f;
                As[kl][mm] = v;
            }
        }
#pragma unroll
        for (int r = 0; r < 2; r++) {
            int idx = tid + r * 256;
            int k = idx >> 5, n4 = (idx & 31) << 2;
            int kg = kt + k;
            float4 v = make_float4(0.f, 0.f, 0.f, 0.f);
            if (kg < DIN) v = *(const float4*)&W[(size_t)kg * HID + n4];
            *(float4*)&Bs[k][n4] = v;
        }
        __syncthreads();
#pragma unroll
        for (int kk = 0; kk < BK; kk++) {
            float a[8], b[8];
            *(float4*)&a[0] = *(float4*)&As[kk][ty * 8];
            *(float4*)&a[4] = *(float4*)&As[kk][ty * 8 + 4];
            *(float4*)&b[0] = *(float4*)&Bs[kk][tx * 8];
            *(float4*)&b[4] = *(float4*)&Bs[kk][tx * 8 + 4];
#pragma unroll
            for (int i = 0; i < 8; i++)
#pragma unroll
                for (int j = 0; j < 8; j++) acc[i][j] += a[i] * b[j];
        }
        __syncthreads();
    }

    float bv[8];
    *(float4*)&bv[0] = *(const float4*)&Bb[tx * 8];
    *(float4*)&bv[4] = *(const float4*)&Bb[tx * 8 + 4];
#pragma unroll
    for (int i = 0; i < 8; i++) {
        int row = gm0 + ty * 8 + i;
        float4 o0, o1;
        o0.x = acc[i][0] + bv[0]; o0.y = acc[i][1] + bv[1];
        o0.z = acc[i][2] + bv[2]; o0.w = acc[i][3] + bv[3];
        o1.x = acc[i][4] + bv[4]; o1.y = acc[i][5] + bv[5];
        o1.z = acc[i][6] + bv[6]; o1.w = acc[i][7] + bv[7];
        *(float4*)&outp[(size_t)row * HID + tx * 8]     = o0;
        *(float4*)&outp[(size_t)row * HID + tx * 8 + 4] = o1;
    }
}

// ---------------------------------------------------------------------------
// Kernel 3: edge scatter. y[e0] += z[e1]; y[e1] += z[e0]. Warp per edge.
// ---------------------------------------------------------------------------
__global__ void k_scatter(const int* __restrict__ edges)
{
    int t = blockIdx.x * blockDim.x + threadIdx.x;
    int e = t >> 5;
    if (e >= E_N) return;
    int c = (t & 31) << 2;
    int a = edges[2 * e + 0];
    int b = edges[2 * e + 1];
    float4 za = *(const float4*)&g_z[(size_t)a * HID + c];
    float4 zb = *(const float4*)&g_z[(size_t)b * HID + c];
    float* ya = &g_y[(size_t)a * HID + c];
    float* yb = &g_y[(size_t)b * HID + c];
    atomicAdd(ya + 0, zb.x); atomicAdd(ya + 1, zb.y);
    atomicAdd(ya + 2, zb.z); atomicAdd(ya + 3, zb.w);
    atomicAdd(yb + 0, za.x); atomicAdd(yb + 1, za.y);
    atomicAdd(yb + 2, za.z); atomicAdd(yb + 3, za.w);
}

// ---------------------------------------------------------------------------
// Kernel 4: g_feats = relu(g_y); optionally also write to output slice.
// ---------------------------------------------------------------------------
__global__ void k_relu(float* __restrict__ out_opt)
{
    size_t i = (size_t)(blockIdx.x * blockDim.x + threadIdx.x) * 4;
    float4 v = *(float4*)&g_y[i];
    v.x = fmaxf(v.x, 0.0f);
    v.y = fmaxf(v.y, 0.0f);
    v.z = fmaxf(v.z, 0.0f);
    v.w = fmaxf(v.w, 0.0f);
    *(float4*)&g_feats[i] = v;
    if (out_opt) *(float4*)&out_opt[i] = v;
}

// ---------------------------------------------------------------------------
// Kernel 5: offset head. new_verts = verts + tanh([feats|verts] @ ow + ob)
// Warp per vertex.
// ---------------------------------------------------------------------------
__global__ void k_offset(const float* __restrict__ verts,
                         const float* __restrict__ ow,
                         const float* __restrict__ ob,
                         float* __restrict__ out)
{
    int gt = blockIdx.x * blockDim.x + threadIdx.x;
    int v = gt >> 5, lane = gt & 31;
    if (v >= V_N) return;
    float a0 = 0.f, a1 = 0.f, a2 = 0.f;
    for (int k = lane; k < DIN; k += 32) {
        float f = (k < HID) ? g_feats[(size_t)v * HID + k]
                            : verts[(size_t)v * 3 + (k - HID)];
        a0 += f * ow[k * 3 + 0];
        a1 += f * ow[k * 3 + 1];
        a2 += f * ow[k * 3 + 2];
    }
#pragma unroll
    for (int o = 16; o; o >>= 1) {
        a0 += __shfl_xor_sync(0xffffffffu, a0, o);
        a1 += __shfl_xor_sync(0xffffffffu, a1, o);
        a2 += __shfl_xor_sync(0xffffffffu, a2, o);
    }
    if (lane == 0) {
        out[(size_t)v * 3 + 0] = verts[(size_t)v * 3 + 0] + tanhf(a0 + ob[0]);
        out[(size_t)v * 3 + 1] = verts[(size_t)v * 3 + 1] + tanhf(a1 + ob[1]);
        out[(size_t)v * 3 + 2] = verts[(size_t)v * 3 + 2] + tanhf(a2 + ob[2]);
    }
}

// ---------------------------------------------------------------------------
extern "C" void kernel_launch(void* const* d_in, const int* in_sizes, int n_in,
                              void* d_out, int out_size)
{
    const float* x     = (const float*)d_in[0];
    const float* verts = (const float*)d_in[1];
    const int*   edges = (const int*)d_in[2];
    const float* bw    = (const float*)d_in[3];
    const float* bb    = (const float*)d_in[4];
    const float* w0    = (const float*)d_in[5];
    const float* b0    = (const float*)d_in[6];
    const float* w1    = (const float*)d_in[7];
    const float* b1    = (const float*)d_in[8];
    const float* ow    = (const float*)d_in[9];
    const float* ob    = (const float*)d_in[10];
    float* out = (float*)d_out;

    // Stage 1: fused sample + bottleneck
    k_img_bottleneck<<<V_N / BM, 256>>>(x, verts, bw, bb);

    // Stage 2: 3 GCN layers
    for (int l = 0; l < 3; l++) {
        dim3 grid(V_N / BM, 2);
        k_gcn_gemm<<<grid, 256>>>(verts,
                                  w0 + (size_t)l * DIN * HID, b0 + (size_t)l * HID,
                                  w1 + (size_t)l * DIN * HID, b1 + (size_t)l * HID);
        k_scatter<<<(E_N * 32) / 256, 256>>>(edges);

        float* out_feats = nullptr;
        if (l == 2 && out_size >= (int)((size_t)V_N * 3 + (size_t)V_N * HID))
            out_feats = out + (size_t)V_N * 3;
        k_relu<<<((size_t)V_N * HID / 4) / 256, 256>>>(out_feats);
    }

    // Stage 3: offset head -> new_verts
    k_offset<<<(V_N * 32) / 256, 256>>>(verts, ow, ob, out);
}